// round 14
// baseline (speedup 1.0000x reference)
#include <cuda_runtime.h>
#include <cuda_fp16.h>
#include <cstdint>

// ---------------------------------------------------------------------------
// ManualCNN round 13: conv2 2 CTAs/SM (single-A, post-mainloop prefetch),
// conv3 384 thr, conv1 direct hi/lo stores via shfl.
// 3-product fp16 split (Ahi*Bhi + Ahi*Blo + Alo*Bhi), fp32 accum.
// ---------------------------------------------------------------------------

#define B_MAX 4096

__device__ half2 g_h1hi[B_MAX * 2592];  // stage1 NHWC padded 18x18, 16ch
__device__ half2 g_h1lo[B_MAX * 2592];
__device__ half2 g_h2hi[B_MAX * 1600];  // stage2 NHWC padded 10x10, 32ch
__device__ half2 g_h2lo[B_MAX * 1600];
__device__ uint4 g_w2pk[1152];          // [hi 576 | lo 576] fragment-packed w2
__device__ uint4 g_w3pk[4608];          // [hi 2304 | lo 2304] fragment-packed w3

typedef unsigned long long u64;

// ------------------------------ scalar helpers -----------------------------
__device__ __forceinline__ u64 pack2(float lo, float hi) {
    u64 r;
    asm("mov.b64 %0, {%1, %2};" : "=l"(r)
        : "r"(__float_as_uint(lo)), "r"(__float_as_uint(hi)));
    return r;
}
__device__ __forceinline__ u64 crossp(u64 a, u64 b) {
    u64 r;
    asm("mov.b64 %0, {%1, %2};" : "=l"(r)
        : "r"((unsigned)(a >> 32)), "r"((unsigned)b));
    return r;
}
__device__ __forceinline__ void fma2(u64& acc, u64 x, u64 w) {
    asm("fma.rn.f32x2 %0, %1, %2, %0;" : "+l"(acc) : "l"(x), "l"(w));
}
__device__ __forceinline__ float lo32(u64 a) { return __uint_as_float((unsigned)a); }
__device__ __forceinline__ float hi32(u64 a) { return __uint_as_float((unsigned)(a >> 32)); }

// ------------------------------- mma helpers -------------------------------
__device__ __forceinline__ void mma_f16(float d[4], const uint32_t a[4],
                                        uint32_t b0, uint32_t b1) {
    asm volatile(
        "mma.sync.aligned.m16n8k16.row.col.f32.f16.f16.f32 "
        "{%0,%1,%2,%3}, {%4,%5,%6,%7}, {%8,%9}, {%0,%1,%2,%3};"
        : "+f"(d[0]), "+f"(d[1]), "+f"(d[2]), "+f"(d[3])
        : "r"(a[0]), "r"(a[1]), "r"(a[2]), "r"(a[3]), "r"(b0), "r"(b1));
}
__device__ __forceinline__ void ldmx4(uint32_t r[4], uint32_t addr) {
    asm volatile("ldmatrix.sync.aligned.m8n8.x4.shared.b16 {%0,%1,%2,%3}, [%4];"
                 : "=r"(r[0]), "=r"(r[1]), "=r"(r[2]), "=r"(r[3]) : "r"(addr));
}
__device__ __forceinline__ uint32_t smem_u32(const void* p) {
    uint32_t a;
    asm("{ .reg .u64 t; cvta.to.shared.u64 t, %1; cvt.u32.u64 %0, t; }"
        : "=r"(a) : "l"(p));
    return a;
}
__device__ __forceinline__ void cp16(uint32_t dst, const void* src) {
    asm volatile("cp.async.cg.shared.global [%0], [%1], 16;"
                 :: "r"(dst), "l"(src) : "memory");
}
__device__ __forceinline__ void cp_commit() {
    asm volatile("cp.async.commit_group;" ::: "memory");
}
__device__ __forceinline__ void cp_wait0() {
    asm volatile("cp.async.wait_group 0;" ::: "memory");
}
__device__ __forceinline__ void cp_wait1() {
    asm volatile("cp.async.wait_group 1;" ::: "memory");
}

// ---------------------------------------------------------------------------
// Stage 1: conv 3->16 on 32x32, pad1, relu, pool2 -> g_h1 hi/lo directly.
// 512 threads: (oc = tid&15, py = (tid>>4)&15, h = tid>>8). Channel pairs
// exchanged via shfl_xor(1); even-oc lanes write half2 hi/lo to gmem.
// ---------------------------------------------------------------------------
__global__ __launch_bounds__(512) void conv1_k(const float* __restrict__ x,
                                               const float* __restrict__ w,
                                               const float* __restrict__ bias) {
    __shared__ __align__(16) float s_in[3][34][38];
    __shared__ float s_w[16 * 28];
    __shared__ float s_b[16];

    const int b = blockIdx.x, tid = threadIdx.x;
    half2* dsthi = g_h1hi + b * 2592;
    half2* dstlo = g_h1lo + b * 2592;

    float* si = &s_in[0][0][0];
    for (int i = tid; i < 3 * 34 * 38; i += 512) si[i] = 0.f;
    if (tid < 432) s_w[(tid / 27) * 28 + (tid % 27)] = w[tid];
    if (tid < 16) s_b[tid] = bias[tid];

    for (int i = tid; i < 544; i += 512) {  // zero gmem halo ring (68 px x 8)
        int hp = i >> 3, j = i & 7, y, xx;
        if (hp < 18)      { y = 0;       xx = hp; }
        else if (hp < 36) { y = 17;      xx = hp - 18; }
        else if (hp < 52) { y = hp - 35; xx = 0; }
        else              { y = hp - 51; xx = 17; }
        dsthi[(y * 18 + xx) * 8 + j] = __floats2half2_rn(0.f, 0.f);
        dstlo[(y * 18 + xx) * 8 + j] = __floats2half2_rn(0.f, 0.f);
    }
    __syncthreads();

    const float4* xb4 = (const float4*)(x + b * 3 * 32 * 32);
    for (int i = tid; i < 768; i += 512) {
        float4 v = xb4[i];
        int base = 4 * i;
        int ic = base >> 10, r = (base >> 5) & 31, c = base & 31;
        s_in[ic][r + 1][c + 1] = v.x;
        s_in[ic][r + 1][c + 2] = v.y;
        s_in[ic][r + 1][c + 3] = v.z;
        s_in[ic][r + 1][c + 4] = v.w;
    }
    __syncthreads();

    const int oc = tid & 15, py = (tid >> 4) & 15, h = tid >> 8;
    const float bb = s_b[oc];

    u64 P0[8], P1[8];
#pragma unroll
    for (int q = 0; q < 8; ++q) { P0[q] = 0ull; P1[q] = 0ull; }
#pragma unroll
    for (int ic = 0; ic < 3; ++ic) {
        u64 wp[9];
#pragma unroll
        for (int k = 0; k < 9; ++k) {
            float wv = s_w[oc * 28 + ic * 9 + k];
            wp[k] = pack2(wv, wv);
        }
#pragma unroll
        for (int r = 0; r < 4; ++r) {
            const float* row = &s_in[ic][2 * py + r][16 * h];
            u64 E[9], O[8];
#pragma unroll
            for (int j = 0; j < 9; ++j) E[j] = *(const u64*)(row + 2 * j);
#pragma unroll
            for (int j = 0; j < 8; ++j) O[j] = crossp(E[j], E[j + 1]);
            if (r < 3) {
#pragma unroll
                for (int q = 0; q < 8; ++q) {
                    fma2(P0[q], E[q],     wp[r * 3 + 0]);
                    fma2(P0[q], O[q],     wp[r * 3 + 1]);
                    fma2(P0[q], E[q + 1], wp[r * 3 + 2]);
                }
            }
            if (r > 0) {
#pragma unroll
                for (int q = 0; q < 8; ++q) {
                    fma2(P1[q], E[q],     wp[(r - 1) * 3 + 0]);
                    fma2(P1[q], O[q],     wp[(r - 1) * 3 + 1]);
                    fma2(P1[q], E[q + 1], wp[(r - 1) * 3 + 2]);
                }
            }
        }
    }

    const int j = oc >> 1;
#pragma unroll
    for (int q = 0; q < 8; ++q) {
        float best = fmaxf(fmaxf(lo32(P0[q]), hi32(P0[q])),
                           fmaxf(lo32(P1[q]), hi32(P1[q])));
        float v = fmaxf(best + bb, 0.f);
        float po = __shfl_xor_sync(0xffffffffu, v, 1);
        if ((oc & 1) == 0) {
            half2 hh = __floats2half2_rn(v, po);
            float2 hf = __half22float2(hh);
            int gi = ((py + 1) * 18 + (8 * h + q + 1)) * 8 + j;
            dsthi[gi] = hh;
            dstlo[gi] = __floats2half2_rn(v - hf.x, po - hf.y);
        }
    }
}

// ---------------------------------------------------------------------------
// Weight prep (layouts unchanged)
// ---------------------------------------------------------------------------
__global__ __launch_bounds__(256) void w2prep_k(const float* __restrict__ w2) {
    int p = blockIdx.x * 256 + threadIdx.x;
    if (p >= 2304) return;
    int s = p >> 8, h = (p >> 7) & 1, l = (p >> 2) & 31, e = p & 3;
    int g = l >> 2, t = l & 3;
    int ky = s / 3, kx = s % 3;
    int oc = (h * 2 + (e >> 1)) * 8 + g;
    int k0 = 2 * t + 8 * (e & 1);
    float v0 = w2[((oc * 16 + k0)     * 3 + ky) * 3 + kx];
    float v1 = w2[((oc * 16 + k0 + 1) * 3 + ky) * 3 + kx];
    half2 hi = __floats2half2_rn(v0, v1);
    float2 hf = __half22float2(hi);
    ((half2*)g_w2pk)[p]        = hi;
    ((half2*)g_w2pk)[2304 + p] = __floats2half2_rn(v0 - hf.x, v1 - hf.y);
}
__global__ __launch_bounds__(256) void w3prep_k(const float* __restrict__ w3) {
    int p = blockIdx.x * 256 + threadIdx.x;
    if (p >= 9216) return;
    int sIdx = p >> 9, np = (p >> 7) & 3, l = (p >> 2) & 31, e = p & 3;
    int g = l >> 2, t = l & 3;
    int s = sIdx >> 1, kb = sIdx & 1;
    int ky = s / 3, kx = s % 3;
    int oc = np * 16 + (e >> 1) * 8 + g;
    int k0 = kb * 16 + 2 * t + 8 * (e & 1);
    float v0 = w3[((oc * 32 + k0)     * 3 + ky) * 3 + kx];
    float v1 = w3[((oc * 32 + k0 + 1) * 3 + ky) * 3 + kx];
    half2 hi = __floats2half2_rn(v0, v1);
    float2 hf = __half22float2(hi);
    ((half2*)g_w3pk)[p]        = hi;
    ((half2*)g_w3pk)[9216 + p] = __floats2half2_rn(v0 - hf.x, v1 - hf.y);
}

// ---------------------------------------------------------------------------
// Stage 2 persistent: conv 16->32, 288 thr, 2 CTAs/SM, single-A buffer.
// Prefetch of next image issued right after the mainloop (A dead).
// smem: [W 18432 | sb 128 | A 31296 | Sg 38016] = 87872 B
// ---------------------------------------------------------------------------
#define C2_SB_OFF 18432
#define C2_A_OFF  18560
#define C2_ALO    15648
#define C2_SG_OFF 49856
#define C2_SMEM   87872
#define RC2(s) ((19 + ((s) / 3 - 1) * 18 + ((s) % 3 - 1)) * 48)

__global__ __launch_bounds__(288, 2) void conv2_p(const float* __restrict__ bias,
                                                  int B) {
    extern __shared__ __align__(16) char sm[];
    const uint4* W4 = (const uint4*)sm;
    float* sb = (float*)(sm + C2_SB_OFF);
    float* Sg = (float*)(sm + C2_SG_OFF);

    const int b0 = blockIdx.x, G = gridDim.x, tid = threadIdx.x;
    const int lane = tid & 31, wid = tid >> 5;
    const uint32_t smb = smem_u32(sm);

    {
        uint4* d = (uint4*)sm;
        for (int i = tid; i < 1152; i += 288) d[i] = g_w2pk[i];
    }
    if (tid < 32) sb[tid] = bias[tid];
    if (tid < 48) {  // zero A margins qp=0,325 (hi+lo)
        int j = tid % 12, r = tid / 12;
        int qp = (r & 1) ? 325 : 0, kind = r >> 1;
        half2* p = (half2*)(sm + C2_A_OFF + kind * C2_ALO);
        p[qp * 12 + j] = __floats2half2_rn(0.f, 0.f);
    }

    const int niter = (B - b0 + G - 1) / G;

    {  // prologue: load image b0
        const uint4* shi = (const uint4*)(g_h1hi + b0 * 2592);
        const uint4* slo = (const uint4*)(g_h1lo + b0 * 2592);
        uint32_t dhi = smb + C2_A_OFF, dlo = dhi + C2_ALO;
        for (int i = tid; i < 648; i += 288) {
            uint32_t off = ((i >> 1) + 1) * 48 + (i & 1) * 16;
            cp16(dhi + off, shi + i);
            cp16(dlo + off, slo + i);
        }
    }
    cp_commit();

    for (int it = 0; it < niter; ++it) {
        const int img = b0 + it * G;
        cp_wait0();
        __syncthreads();

        const uint32_t aHiB = smb + C2_A_OFF + (lane & 15) * 48 + (lane >> 4) * 16;
        const uint32_t aLoB = aHiB + C2_ALO;
        const int mt0 = 2 * wid;

        float d[2][4][4];
#pragma unroll
        for (int i = 0; i < 2; ++i)
#pragma unroll
            for (int nt = 0; nt < 4; ++nt)
#pragma unroll
                for (int k = 0; k < 4; ++k) d[i][nt][k] = 0.f;

        uint32_t ah[2][4], al[2][4];
        ldmx4(ah[0], aHiB + RC2(0) + mt0 * 768);
        ldmx4(al[0], aLoB + RC2(0) + mt0 * 768);

#pragma unroll
        for (int s = 0; s < 9; ++s) {
            const uint4 h0 = W4[(s * 2 + 0) * 32 + lane];
            const uint4 h1 = W4[(s * 2 + 1) * 32 + lane];
            const uint4 l0 = W4[576 + (s * 2 + 0) * 32 + lane];
            const uint4 l1 = W4[576 + (s * 2 + 1) * 32 + lane];
#pragma unroll
            for (int i = 0; i < 2; ++i) {
                const int stp = 2 * s + i, p = stp & 1, pn = p ^ 1;
                if (stp + 1 < 18) {
                    const int ns = (i == 0) ? s : s + 1;
                    const int nmt = (i == 0) ? mt0 + 1 : mt0;
                    ldmx4(ah[pn], aHiB + RC2(ns) + nmt * 768);
                    ldmx4(al[pn], aLoB + RC2(ns) + nmt * 768);
                }
                mma_f16(d[i][0], ah[p], h0.x, h0.y);
                mma_f16(d[i][0], ah[p], l0.x, l0.y);
                mma_f16(d[i][0], al[p], h0.x, h0.y);
                mma_f16(d[i][1], ah[p], h0.z, h0.w);
                mma_f16(d[i][1], ah[p], l0.z, l0.w);
                mma_f16(d[i][1], al[p], h0.z, h0.w);
                mma_f16(d[i][2], ah[p], h1.x, h1.y);
                mma_f16(d[i][2], ah[p], l1.x, l1.y);
                mma_f16(d[i][2], al[p], h1.x, h1.y);
                mma_f16(d[i][3], ah[p], h1.z, h1.w);
                mma_f16(d[i][3], ah[p], l1.z, l1.w);
                mma_f16(d[i][3], al[p], h1.z, h1.w);
            }
        }
        __syncthreads();  // all A reads done

        const int nxt = img + G;
        if (nxt < B) {  // prefetch next image into A (overlaps epilogue)
            const uint4* shi = (const uint4*)(g_h1hi + nxt * 2592);
            const uint4* slo = (const uint4*)(g_h1lo + nxt * 2592);
            uint32_t dhi = smb + C2_A_OFF, dlo = dhi + C2_ALO;
            for (int i = tid; i < 648; i += 288) {
                uint32_t off = ((i >> 1) + 1) * 48 + (i & 1) * 16;
                cp16(dhi + off, shi + i);
                cp16(dlo + off, slo + i);
            }
        }
        cp_commit();

        const int g = lane >> 2, t = lane & 3;
#pragma unroll
        for (int i = 0; i < 2; ++i) {
            const int row = 16 * (mt0 + i) + g;
#pragma unroll
            for (int nt = 0; nt < 4; ++nt) {
                const int col = nt * 8 + 2 * t;
                Sg[row * 33 + col]           = fmaxf(d[i][nt][0] + sb[col], 0.f);
                Sg[row * 33 + col + 1]       = fmaxf(d[i][nt][1] + sb[col + 1], 0.f);
                Sg[(row + 8) * 33 + col]     = fmaxf(d[i][nt][2] + sb[col], 0.f);
                Sg[(row + 8) * 33 + col + 1] = fmaxf(d[i][nt][3] + sb[col + 1], 0.f);
            }
        }
        __syncthreads();

        for (int e = tid; e < 1024; e += 288) {
            int oc2 = e & 15, pp = e >> 4;
            int py = pp >> 3, px = pp & 7;
            int r0 = 18 * (2 * py + 1) + (2 * px + 1) - 18;
            int c0 = 2 * oc2;
            float v0 = fmaxf(fmaxf(Sg[r0 * 33 + c0], Sg[(r0 + 1) * 33 + c0]),
                             fmaxf(Sg[(r0 + 18) * 33 + c0], Sg[(r0 + 19) * 33 + c0]));
            float v1 = fmaxf(fmaxf(Sg[r0 * 33 + c0 + 1], Sg[(r0 + 1) * 33 + c0 + 1]),
                             fmaxf(Sg[(r0 + 18) * 33 + c0 + 1], Sg[(r0 + 19) * 33 + c0 + 1]));
            half2 hh = __floats2half2_rn(v0, v1);
            float2 hf = __half22float2(hh);
            int gi = img * 1600 + ((py + 1) * 10 + (px + 1)) * 16 + oc2;
            g_h2hi[gi] = hh;
            g_h2lo[gi] = __floats2half2_rn(v0 - hf.x, v1 - hf.y);
        }
        for (int i = tid; i < 576; i += 288) {
            int hp = i >> 4, c = i & 15, y, xx;
            if (hp < 10)      { y = 0;       xx = hp; }
            else if (hp < 20) { y = 9;       xx = hp - 10; }
            else if (hp < 28) { y = hp - 19; xx = 0; }
            else              { y = hp - 27; xx = 9; }
            int gi = img * 1600 + (y * 10 + xx) * 16 + c;
            g_h2hi[gi] = __floats2half2_rn(0.f, 0.f);
            g_h2lo[gi] = __floats2half2_rn(0.f, 0.f);
        }
    }
}

// ---------------------------------------------------------------------------
// Stage 3 persistent + fused FC, 384 thr / 12 warps, double-buffered A.
// Warp w: np=w&3 (16 oc), mg=w>>2 (0..2), m-tiles {2mg, 2mg+1}.
// smem: [W 73728|sb|fcb|red|fcw 40960|A 2x18880|Sg 24960] = 178240 B
// ---------------------------------------------------------------------------
#define C3_SB_OFF 73728
#define C3_FCB    73984
#define C3_RED    74048
#define C3_FCW    74560
#define C3_A_OFF  115520
#define C3_ALO    9440
#define C3_ABUF   18880
#define C3_SG_OFF 153280
#define C3_SMEM   178240
#define RC3(si) ((11 + (((si) >> 1) / 3 - 1) * 10 + (((si) >> 1) % 3 - 1)) * 80 + ((si) & 1) * 32)

__global__ __launch_bounds__(384, 1) void conv3_p(const float* __restrict__ bias,
                                                  const float* __restrict__ fw,
                                                  const float* __restrict__ fb,
                                                  float* __restrict__ out, int B) {
    extern __shared__ __align__(16) char sm[];
    const uint4* W4 = (const uint4*)sm;
    float* sb  = (float*)(sm + C3_SB_OFF);
    float* fcb = (float*)(sm + C3_FCB);
    float* red = (float*)(sm + C3_RED);
    float* fcw = (float*)(sm + C3_FCW);
    float* Sg  = (float*)(sm + C3_SG_OFF);

    const int b0 = blockIdx.x, G = gridDim.x, tid = threadIdx.x;
    const int lane = tid & 31, wid = tid >> 5;
    const uint32_t smb = smem_u32(sm);

    {
        uint4* d = (uint4*)sm;
        for (int i = tid; i < 4608; i += 384) d[i] = g_w3pk[i];
    }
    if (tid < 64) sb[tid] = bias[tid];
    if (tid < 10) fcb[tid] = fb[tid];
    for (int i = tid; i < 10240; i += 384) fcw[i] = fw[i];
    for (int i = tid; i < 1440; i += 384) {  // zero A margins qp 0..2, 103..117
        int j = i % 20, r = i / 20;
        int pxi = r % 18, kb = r / 18;
        int qp = (pxi < 3) ? pxi : (100 + pxi);
        half2* p = (half2*)(sm + C3_A_OFF + (kb >> 1) * C3_ABUF + (kb & 1) * C3_ALO);
        p[qp * 20 + j] = __floats2half2_rn(0.f, 0.f);
    }

    const int niter = (B - b0 + G - 1) / G;

    {
        const uint4* shi = (const uint4*)(g_h2hi + b0 * 1600);
        const uint4* slo = (const uint4*)(g_h2lo + b0 * 1600);
        uint32_t dhi = smb + C3_A_OFF, dlo = dhi + C3_ALO;
        for (int i = tid; i < 400; i += 384) {
            uint32_t off = ((i >> 2) + 3) * 80 + (i & 3) * 16;
            cp16(dhi + off, shi + i);
            cp16(dlo + off, slo + i);
        }
    }
    cp_commit();

    for (int it = 0; it < niter; ++it) {
        const int img = b0 + it * G;
        const int nxt = img + G;
        if (nxt < B) {
            const uint4* shi = (const uint4*)(g_h2hi + nxt * 1600);
            const uint4* slo = (const uint4*)(g_h2lo + nxt * 1600);
            uint32_t dhi = smb + C3_A_OFF + ((it + 1) & 1) * C3_ABUF;
            uint32_t dlo = dhi + C3_ALO;
            for (int i = tid; i < 400; i += 384) {
                uint32_t off = ((i >> 2) + 3) * 80 + (i & 3) * 16;
                cp16(dhi + off, shi + i);
                cp16(dlo + off, slo + i);
            }
        }
        cp_commit();
        cp_wait1();
        __syncthreads();

        const uint32_t aHiB = smb + C3_A_OFF + (it & 1) * C3_ABUF +
                              (lane & 15) * 80 + (lane >> 4) * 16;
        const uint32_t aLoB = aHiB + C3_ALO;
        const int np = wid & 3, mg = wid >> 2;
        const int mt0 = 2 * mg;

        float d[2][2][4];
#pragma unroll
        for (int i = 0; i < 2; ++i)
#pragma unroll
            for (int nt = 0; nt < 2; ++nt)
#pragma unroll
                for (int k = 0; k < 4; ++k) d[i][nt][k] = 0.f;

        uint32_t ah[2][4], al[2][4];
        uint4 Wb[2][2];
        ldmx4(ah[0], aHiB + RC3(0) + mt0 * 1280);
        ldmx4(al[0], aLoB + RC3(0) + mt0 * 1280);
        Wb[0][0] = W4[(0 * 4 + np) * 32 + lane];
        Wb[0][1] = W4[2304 + (0 * 4 + np) * 32 + lane];

#pragma unroll
        for (int sIdx = 0; sIdx < 18; ++sIdx) {
            const int cw = sIdx & 1, nw = cw ^ 1;
            if (sIdx < 17) {
                Wb[nw][0] = W4[((sIdx + 1) * 4 + np) * 32 + lane];
                Wb[nw][1] = W4[2304 + ((sIdx + 1) * 4 + np) * 32 + lane];
            }
#pragma unroll
            for (int i = 0; i < 2; ++i) {
                const int stp = 2 * sIdx + i, p = stp & 1, pn = p ^ 1;
                if (stp + 1 < 36) {
                    const int ns = (i == 0) ? sIdx : sIdx + 1;
                    const int nmt = (i == 0) ? mt0 + 1 : mt0;
                    ldmx4(ah[pn], aHiB + RC3(ns) + nmt * 1280);
                    ldmx4(al[pn], aLoB + RC3(ns) + nmt * 1280);
                }
                mma_f16(d[i][0], ah[p], Wb[cw][0].x, Wb[cw][0].y);
                mma_f16(d[i][0], ah[p], Wb[cw][1].x, Wb[cw][1].y);
                mma_f16(d[i][0], al[p], Wb[cw][0].x, Wb[cw][0].y);
                mma_f16(d[i][1], ah[p], Wb[cw][0].z, Wb[cw][0].w);
                mma_f16(d[i][1], ah[p], Wb[cw][1].z, Wb[cw][1].w);
                mma_f16(d[i][1], al[p], Wb[cw][0].z, Wb[cw][0].w);
            }
        }
        __syncthreads();

        const int g = lane >> 2, t = lane & 3;
#pragma unroll
        for (int i = 0; i < 2; ++i) {
            const int row = 16 * (mt0 + i) + g;
#pragma unroll
            for (int nt = 0; nt < 2; ++nt) {
                const int col = np * 16 + nt * 8 + 2 * t;
                Sg[row * 65 + col]           = fmaxf(d[i][nt][0] + sb[col], 0.f);
                Sg[row * 65 + col + 1]       = fmaxf(d[i][nt][1] + sb[col + 1], 0.f);
                Sg[(row + 8) * 65 + col]     = fmaxf(d[i][nt][2] + sb[col], 0.f);
                Sg[(row + 8) * 65 + col + 1] = fmaxf(d[i][nt][3] + sb[col + 1], 0.f);
            }
        }
        __syncthreads();

        // ---- pool + fused FC
        float acc[10];
#pragma unroll
        for (int o = 0; o < 10; ++o) acc[o] = 0.f;
        for (int e = tid; e < 1024; e += 384) {
            int oc = e >> 4, pp = e & 15, py = pp >> 2, px = pp & 3;
            int r0 = 10 * (2 * py + 1) + (2 * px + 1) - 8;
            float v = fmaxf(fmaxf(Sg[r0 * 65 + oc], Sg[(r0 + 1) * 65 + oc]),
                            fmaxf(Sg[(r0 + 10) * 65 + oc], Sg[(r0 + 11) * 65 + oc]));
#pragma unroll
            for (int o = 0; o < 10; ++o)
                acc[o] = fmaf(v, fcw[o * 1024 + e], acc[o]);
        }
#pragma unroll
        for (int o = 0; o < 10; ++o) {
#pragma unroll
            for (int off = 16; off; off >>= 1)
                acc[o] += __shfl_down_sync(0xffffffffu, acc[o], off);
        }
        if (lane == 0) {
#pragma unroll
            for (int o = 0; o < 10; ++o) red[wid * 10 + o] = acc[o];
        }
        __syncthreads();
        if (tid < 10) {
            float s2 = fcb[tid];
#pragma unroll
            for (int w12 = 0; w12 < 12; ++w12) s2 += red[w12 * 10 + tid];
            out[img * 10 + tid] = s2;
        }
    }
}

// ---------------------------------------------------------------------------
extern "C" void kernel_launch(void* const* d_in, const int* in_sizes, int n_in,
                              void* d_out, int out_size) {
    const float* x  = (const float*)d_in[0];
    const float* w1 = (const float*)d_in[1];
    const float* b1 = (const float*)d_in[2];
    const float* w2 = (const float*)d_in[3];
    const float* b2 = (const float*)d_in[4];
    const float* w3 = (const float*)d_in[5];
    const float* b3 = (const float*)d_in[6];
    const float* fw = (const float*)d_in[7];
    const float* fb = (const float*)d_in[8];
    float* out = (float*)d_out;

    const int B = in_sizes[0] / (3 * 32 * 32);

    cudaFuncSetAttribute(conv2_p, cudaFuncAttributeMaxDynamicSharedMemorySize, C2_SMEM);
    cudaFuncSetAttribute(conv3_p, cudaFuncAttributeMaxDynamicSharedMemorySize, C3_SMEM);
    cudaFuncSetAttribute(conv2_p, cudaFuncAttributePreferredSharedMemoryCarveout, 100);
    cudaFuncSetAttribute(conv3_p, cudaFuncAttributePreferredSharedMemoryCarveout, 100);

    w2prep_k<<<9, 256>>>(w2);
    w3prep_k<<<36, 256>>>(w3);
    conv1_k<<<B, 512>>>(x, w1, b1);
    conv2_p<<<296, 288, C2_SMEM>>>(b2, B);
    conv3_p<<<148, 384, C3_SMEM>>>(b3, fw, fb, out, B);
}